// round 11
// baseline (speedup 1.0000x reference)
#include <cuda_runtime.h>
#include <cuda_bf16.h>
#include <cstdint>

#define CC 512
#define TT 8192
#define SEG_T 32
#define SEGS 256                 // TT / SEG_T
#define NCTA 4096                // 16 batch * 256 segs
#define NTHREADS 256
#define DIVC 512.0f
#define EPSV 1e-8f
#define FULL 0xffffffffu

// one 16B record per segment: {s, q, flag, pad}; flag 0=empty, 1=aggregate, 2=prefix
__device__ float4 g_rec[NCTA];

__global__ void init_rec_kernel() {
    int i = blockIdx.x * blockDim.x + threadIdx.x;
    if (i < NCTA) g_rec[i] = make_float4(0.f, 0.f, 0.f, 0.f);
}

__device__ __forceinline__ float4 ld_rec_vol(const float4* p) {
    float4 r;
    asm volatile("ld.volatile.global.v4.f32 {%0,%1,%2,%3}, [%4];"
                 : "=f"(r.x), "=f"(r.y), "=f"(r.z), "=f"(r.w) : "l"(p));
    return r;
}
__device__ __forceinline__ void st_rec_vol(float4* p, float s, float q, int flag) {
    asm volatile("st.volatile.global.v4.f32 [%0], {%1,%2,%3,%4};"
                 :: "l"(p), "f"(s), "f"(q), "f"(__int_as_float(flag)), "f"(0.f)
                 : "memory");
}

__global__ void __launch_bounds__(NTHREADS, 4)
newNormal_kernel(const float* __restrict__ x,
                 const float* __restrict__ gains,
                 const float* __restrict__ bias,
                 float* __restrict__ out) {
    __shared__ float4 ps[8][8];          // [warp][chunk] channel-sum partials  1 KB
    __shared__ float4 pq[8][8];
    __shared__ float4 mean4[8], inv4[8];

    const int bid  = blockIdx.x;
    const int b    = bid >> 8;           // batch
    const int seg  = bid & 255;          // segment within row (ascending bid)
    const int t0   = seg * SEG_T;
    const int tid  = threadIdx.x;
    const int lane = tid & 31;
    const int w    = tid >> 5;           // 8 warps
    const int chunk = tid & 7;           // fixed 4-t chunk (32 t total)
    const int rp    = tid >> 3;          // 0..31: channel phase

    const float* xb = x + ((size_t)b * CC) * TT + t0 + 4 * chunk;

    // ======== Pass 1: warp-contiguous streaming read + per-chunk sums ========
    // warp touches 4 channel rows x 128B contiguous each -> nL=4 per LDG.128
    float4 s4 = make_float4(0.f, 0.f, 0.f, 0.f);
    float4 q4 = make_float4(0.f, 0.f, 0.f, 0.f);
#pragma unroll
    for (int iblk = 0; iblk < 2; iblk++) {
        float4 v[8];
#pragma unroll
        for (int u = 0; u < 8; u++) {
            const int c = (iblk * 8 + u) * 32 + rp;       // channel
            v[u] = __ldg((const float4*)(xb + (size_t)c * TT));
        }
#pragma unroll
        for (int u = 0; u < 8; u++) {
            float4 t = v[u];
            s4.x += t.x; s4.y += t.y; s4.z += t.z; s4.w += t.w;
            q4.x = fmaf(t.x, t.x, q4.x); q4.y = fmaf(t.y, t.y, q4.y);
            q4.z = fmaf(t.z, t.z, q4.z); q4.w = fmaf(t.w, t.w, q4.w);
        }
    }
    // reduce the 4 channel-phases within the warp (lanes chunk, chunk+8, +16, +24)
#pragma unroll
    for (int d = 16; d >= 8; d >>= 1) {
        s4.x += __shfl_down_sync(FULL, s4.x, d); s4.y += __shfl_down_sync(FULL, s4.y, d);
        s4.z += __shfl_down_sync(FULL, s4.z, d); s4.w += __shfl_down_sync(FULL, s4.w, d);
        q4.x += __shfl_down_sync(FULL, q4.x, d); q4.y += __shfl_down_sync(FULL, q4.y, d);
        q4.z += __shfl_down_sync(FULL, q4.z, d); q4.w += __shfl_down_sync(FULL, q4.w, d);
    }
    if (lane < 8) { ps[w][lane] = s4; pq[w][lane] = q4; }
    __syncthreads();

    // ======== warp 0: final reduce + scan 32 + shallow look-back ========
    if (tid < 32) {
        float4 sv = make_float4(0.f,0.f,0.f,0.f), qv = make_float4(0.f,0.f,0.f,0.f);
        if (lane < 8) {
#pragma unroll
            for (int w2 = 0; w2 < 8; w2++) {
                float4 a = ps[w2][lane];
                sv.x += a.x; sv.y += a.y; sv.z += a.z; sv.w += a.w;
                float4 c = pq[w2][lane];
                qv.x += c.x; qv.y += c.y; qv.z += c.z; qv.w += c.w;
            }
        }
        // inclusive scan within the 4-t chunk
        float4 is, iq;
        is.x = sv.x; is.y = is.x + sv.y; is.z = is.y + sv.z; is.w = is.z + sv.w;
        iq.x = qv.x; iq.y = iq.x + qv.y; iq.z = iq.y + qv.z; iq.w = iq.z + qv.w;
        // scan chunk totals across lanes 0..7
        const float gs = is.w, gq = iq.w;
        float ssc = gs, qsc = gq;
#pragma unroll
        for (int d = 1; d < 8; d <<= 1) {
            float a = __shfl_up_sync(FULL, ssc, d);
            float c = __shfl_up_sync(FULL, qsc, d);
            if (lane >= d && lane < 8) { ssc += a; qsc += c; }
        }
        const float exg_s = ssc - gs, exg_q = qsc - gq;
        const float tot_s = __shfl_sync(FULL, ssc, 7);
        const float tot_q = __shfl_sync(FULL, qsc, 7);

        // decoupled look-back, depth <= 255 (warp-parallel, 32 records/round;
        // earlier-wave predecessors carry flag=2 -> immediate cut)
        float ex_s = 0.f, ex_q = 0.f;
        if (seg == 0) {
            if (lane == 0) st_rec_vol(&g_rec[bid], tot_s, tot_q, 2);
        } else {
            if (lane == 0) st_rec_vol(&g_rec[bid], tot_s, tot_q, 1);
            const int base = bid - seg;
            int p_hi = bid - 1;
            for (;;) {
                const int p = p_hi - lane;
                float rs, rq; int f;
                if (p >= base) {
                    float4 rr2 = ld_rec_vol(&g_rec[p]);
                    rs = rr2.x; rq = rr2.y; f = __float_as_int(rr2.z);
                } else { rs = 0.f; rq = 0.f; f = 2; }
                if (__ballot_sync(FULL, f == 0)) { __nanosleep(32); continue; }
                const unsigned m2 = __ballot_sync(FULL, f == 2);
                float cs, cq;
                if (m2) {
                    const int l2 = __ffs(m2) - 1;
                    cs = (lane <= l2) ? rs : 0.f;
                    cq = (lane <= l2) ? rq : 0.f;
                } else { cs = rs; cq = rq; }
#pragma unroll
                for (int d = 16; d; d >>= 1) {
                    cs += __shfl_down_sync(FULL, cs, d);
                    cq += __shfl_down_sync(FULL, cq, d);
                }
                ex_s += __shfl_sync(FULL, cs, 0);
                ex_q += __shfl_sync(FULL, cq, 0);
                if (m2) break;
                p_hi -= 32;
            }
            if (lane == 0) st_rec_vol(&g_rec[bid], ex_s + tot_s, ex_q + tot_q, 2);
        }

        // mean / rsqrt per t chunk
        if (lane < 8) {
            const float bs = ex_s + exg_s;
            const float bq = ex_q + exg_q;
            const int tb = t0 + 4 * lane;
            float4 m4, i4;
            {
                float dv = 1.0f / ((float)(tb + 1) * DIVC);
                float m = (bs + is.x) * dv;
                float var = fmaf(-m, m, (bq + iq.x) * dv);
                m4.x = m; i4.x = rsqrtf(var + EPSV);
            }
            {
                float dv = 1.0f / ((float)(tb + 2) * DIVC);
                float m = (bs + is.y) * dv;
                float var = fmaf(-m, m, (bq + iq.y) * dv);
                m4.y = m; i4.y = rsqrtf(var + EPSV);
            }
            {
                float dv = 1.0f / ((float)(tb + 3) * DIVC);
                float m = (bs + is.z) * dv;
                float var = fmaf(-m, m, (bq + iq.z) * dv);
                m4.z = m; i4.z = rsqrtf(var + EPSV);
            }
            {
                float dv = 1.0f / ((float)(tb + 4) * DIVC);
                float m = (bs + is.w) * dv;
                float var = fmaf(-m, m, (bq + iq.w) * dv);
                m4.w = m; i4.w = rsqrtf(var + EPSV);
            }
            mean4[lane] = m4;
            inv4[lane]  = i4;
        }
    }
    __syncthreads();

    // ======== Pass 2: re-read own 64KB (L2-hot), normalize, write ========
    {
        const float4 m4 = mean4[chunk];
        const float4 i4 = inv4[chunk];
        float* ob = out + ((size_t)b * CC) * TT + t0 + 4 * chunk;
#pragma unroll
        for (int iblk = 0; iblk < 2; iblk++) {
            float4 v[8];
            float gg[8], bb[8];
#pragma unroll
            for (int u = 0; u < 8; u++) {
                const int c = (iblk * 8 + u) * 32 + rp;
                v[u]  = __ldg((const float4*)(xb + (size_t)c * TT));
                gg[u] = __ldg(gains + c);
                bb[u] = __ldg(bias  + c);
            }
#pragma unroll
            for (int u = 0; u < 8; u++) {
                const int c = (iblk * 8 + u) * 32 + rp;
                float4 t = v[u];
                float4 o;
                o.x = fmaf((t.x - m4.x) * i4.x, gg[u], bb[u]);
                o.y = fmaf((t.y - m4.y) * i4.y, gg[u], bb[u]);
                o.z = fmaf((t.z - m4.z) * i4.z, gg[u], bb[u]);
                o.w = fmaf((t.w - m4.w) * i4.w, gg[u], bb[u]);
                __stcs((float4*)(ob + (size_t)c * TT), o);
            }
        }
    }
}

extern "C" void kernel_launch(void* const* d_in, const int* in_sizes, int n_in,
                              void* d_out, int out_size) {
    (void)in_sizes; (void)n_in; (void)out_size;
    const float* x     = (const float*)d_in[0];
    const float* gains = (const float*)d_in[1];
    const float* bias  = (const float*)d_in[2];
    float* out = (float*)d_out;

    init_rec_kernel<<<NCTA / 256, 256>>>();
    newNormal_kernel<<<NCTA, NTHREADS>>>(x, gains, bias, out);
}